// round 13
// baseline (speedup 1.0000x reference)
#include <cuda_runtime.h>
#include <cuda_bf16.h>
#include <math.h>
#include <stdint.h>

// ---------------------------------------------------------------------------
// Problem constants
// ---------------------------------------------------------------------------
#define B_      2
#define M_      2048
#define DMODEL  1024
#define NH      16
#define DK      64
#define FF      4096
#define ROWS    (B_ * M_)          // 4096
#define MASKF   (-9.765625e11f)    // MASK_VAL / D_MODEL
#define INV_D   (1.0f / 1024.0f)
#define LN_EPS  1e-5f

// ---------------------------------------------------------------------------
// Scratch (allocation-free: __device__ globals)
// ---------------------------------------------------------------------------
__device__ float g_Q [ROWS * DMODEL];
__device__ float g_K [ROWS * DMODEL];
__device__ float g_V [ROWS * DMODEL];
__device__ float g_AO[ROWS * DMODEL];
__device__ float g_H1[ROWS * DMODEL];
__device__ float g_F1[ROWS * FF];        // aliased as two bf16 planes (hi|lo)
__device__ float g_F2[ROWS * DMODEL];
__device__ unsigned char g_mask[ROWS];
__device__ __nv_bfloat16 g_Ah[ROWS * DMODEL];
__device__ __nv_bfloat16 g_Al[ROWS * DMODEL];
__device__ __nv_bfloat16 g_Bh[FF * DMODEL];
__device__ __nv_bfloat16 g_Bl[FF * DMODEL];

// ---------------------------------------------------------------------------
// Helpers
// ---------------------------------------------------------------------------
__device__ __forceinline__ uint32_t smem_u32(const void* p) {
    uint32_t a;
    asm("{ .reg .u64 t; cvta.to.shared.u64 t, %1; cvt.u32.u64 %0, t; }"
        : "=r"(a) : "l"(p));
    return a;
}

__device__ __forceinline__ void cp_async16(uint32_t saddr, const void* g) {
    asm volatile("cp.async.cg.shared.global [%0], [%1], 16;"
                 :: "r"(saddr), "l"(g));
}
#define CP_COMMIT()  asm volatile("cp.async.commit_group;" ::: "memory")
#define CP_WAIT(n)   asm volatile("cp.async.wait_group %0;" :: "n"(n) : "memory")

__device__ __forceinline__ void ldsm_x4(uint32_t* r, uint32_t addr) {
    asm volatile("ldmatrix.sync.aligned.m8n8.x4.shared.b16 {%0,%1,%2,%3}, [%4];"
                 : "=r"(r[0]), "=r"(r[1]), "=r"(r[2]), "=r"(r[3]) : "r"(addr));
}

__device__ __forceinline__ void ldsm_x4_t(uint32_t* r, uint32_t addr) {
    asm volatile("ldmatrix.sync.aligned.m8n8.x4.trans.shared.b16 {%0,%1,%2,%3}, [%4];"
                 : "=r"(r[0]), "=r"(r[1]), "=r"(r[2]), "=r"(r[3]) : "r"(addr));
}

__device__ __forceinline__ void mma_bf16(float* c, const uint32_t* a, const uint32_t* b) {
    asm volatile(
        "mma.sync.aligned.m16n8k16.row.col.f32.bf16.bf16.f32 "
        "{%0,%1,%2,%3}, {%4,%5,%6,%7}, {%8,%9}, {%0,%1,%2,%3};"
        : "+f"(c[0]), "+f"(c[1]), "+f"(c[2]), "+f"(c[3])
        : "r"(a[0]), "r"(a[1]), "r"(a[2]), "r"(a[3]), "r"(b[0]), "r"(b[1]));
}

// pack two fp32 -> bf16x2 (first arg in low half)
__device__ __forceinline__ uint32_t cvt_bf2(float lo, float hi) {
    uint32_t r;
    asm("cvt.rn.bf16x2.f32 %0, %1, %2;" : "=r"(r) : "f"(hi), "f"(lo));
    return r;
}

// ---------------------------------------------------------------------------
// Mask normalization (unchanged, known-correct)
// ---------------------------------------------------------------------------
__global__ void mask_norm_kernel(const unsigned char* __restrict__ mb, int nelem)
{
    __shared__ int s_gt1, s_off;
    int t = threadIdx.x;
    if (t == 0) { s_gt1 = 0; s_off = 0; }
    __syncthreads();
    int gt1 = 0, off = 0;
    for (int i = t; i < nelem; i += blockDim.x) {
        unsigned char v = mb[i];
        if (v > 1) gt1 = 1;
        if ((i & 3) && v) off = 1;
    }
    if (gt1) atomicOr(&s_gt1, 1);
    if (off) atomicOr(&s_off, 1);
    __syncthreads();
    bool u8 = (!s_gt1) && s_off;
    if (u8) {
        for (int i = t; i < nelem; i += blockDim.x)
            g_mask[i] = mb[i] ? 1 : 0;
    } else {
        const int* mi = (const int*)mb;
        for (int i = t; i < nelem; i += blockDim.x)
            g_mask[i] = mi[i] ? 1 : 0;
    }
}

// ---------------------------------------------------------------------------
// fp32 -> bf16 hi/lo split (x only)
// ---------------------------------------------------------------------------
__global__ __launch_bounds__(256)
void conv_split_kernel(const float* __restrict__ src,
                       __nv_bfloat16* __restrict__ hi, __nv_bfloat16* __restrict__ lo,
                       int n4)
{
    int i = blockIdx.x * 256 + threadIdx.x;
    if (i >= n4) return;
    float4 v = ((const float4*)src)[i];
    __nv_bfloat16 h0 = __float2bfloat16(v.x);
    __nv_bfloat16 h1 = __float2bfloat16(v.y);
    __nv_bfloat16 h2 = __float2bfloat16(v.z);
    __nv_bfloat16 h3 = __float2bfloat16(v.w);
    __nv_bfloat16 l0 = __float2bfloat16(v.x - __bfloat162float(h0));
    __nv_bfloat16 l1 = __float2bfloat16(v.y - __bfloat162float(h1));
    __nv_bfloat16 l2 = __float2bfloat16(v.z - __bfloat162float(h2));
    __nv_bfloat16 l3 = __float2bfloat16(v.w - __bfloat162float(h3));
    __nv_bfloat162* H = (__nv_bfloat162*)hi;
    __nv_bfloat162* L = (__nv_bfloat162*)lo;
    H[2 * i]     = __nv_bfloat162(h0, h1);
    H[2 * i + 1] = __nv_bfloat162(h2, h3);
    L[2 * i]     = __nv_bfloat162(l0, l1);
    L[2 * i + 1] = __nv_bfloat162(l2, l3);
}

// ---------------------------------------------------------------------------
// Weight transpose + split: src[K,N] fp32 -> hi/lo [N,K] bf16
// ---------------------------------------------------------------------------
__global__ __launch_bounds__(256)
void convT_split_kernel(const float* __restrict__ src,
                        __nv_bfloat16* __restrict__ hi, __nv_bfloat16* __restrict__ lo,
                        int Kdim, int Ndim)
{
    __shared__ float tile[32][33];
    int n0 = blockIdx.x * 32, k0 = blockIdx.y * 32;
    int x = threadIdx.x, y = threadIdx.y;   // 32 x 8
#pragma unroll
    for (int j = 0; j < 32; j += 8)
        tile[y + j][x] = src[(size_t)(k0 + y + j) * Ndim + n0 + x];
    __syncthreads();
#pragma unroll
    for (int j = 0; j < 32; j += 8) {
        float v = tile[x][y + j];
        __nv_bfloat16 h = __float2bfloat16(v);
        __nv_bfloat16 l = __float2bfloat16(v - __bfloat162float(h));
        size_t o = (size_t)(n0 + y + j) * Kdim + k0 + x;
        hi[o] = h; lo[o] = l;
    }
}

// ---------------------------------------------------------------------------
// HMMA GEMM v3: R5 triple-pass dataflow with BK=64 (half the barriers).
// Dynamic smem: 2 stages x (A,B) x 128x72 bf16 = 72KB. 8 warps (4x2).
// mode: 0 = fp32 out + bias; 1 = +relu fp32; 2 = +relu, write bf16 hi/lo split.
// ---------------------------------------------------------------------------
#define HLD2   72                        // 64 + 8 pad (bf16 elems)
#define TILEB  (128 * HLD2 * 2)          // 18432 bytes per tile
#define STGB   (2 * TILEB)               // A+B per stage
#define GEMM_SMEM (2 * STGB)             // 73728 bytes

__global__ __launch_bounds__(256, 2)
void hgemm_bf16x3_kernel(const __nv_bfloat16* __restrict__ Ahm,
                         const __nv_bfloat16* __restrict__ Alm,
                         const __nv_bfloat16* __restrict__ Bhm,
                         const __nv_bfloat16* __restrict__ Blm,
                         const float* __restrict__ bias,
                         float* __restrict__ C,
                         __nv_bfloat16* __restrict__ Chi,
                         __nv_bfloat16* __restrict__ Clo,
                         int Ndim, int Kdim, int mode)
{
    extern __shared__ char dsm[];
    const uint32_t sb = smem_u32(dsm);

    const int tid  = threadIdx.x;
    const int lane = tid & 31;
    const int wid  = tid >> 5;
    const int bm = blockIdx.y, bn = blockIdx.x;
    const int wm = (wid >> 1) * 32;
    const int wn = (wid & 1) * 64;

    const int nk = Kdim >> 6;            // 64-wide K chunks
    const int nIter = 3 * nk;

    const int lrow = tid >> 3;           // 0..31 (x4 rounds -> 0..127)
    const int lch  = tid & 7;            // 0..7 -> col = lch*8

    float acc[2][8][4];
#pragma unroll
    for (int mi = 0; mi < 2; mi++)
#pragma unroll
        for (int nj = 0; nj < 8; nj++)
#pragma unroll
            for (int q = 0; q < 4; q++) acc[mi][nj][q] = 0.0f;

    auto load_stage = [&](int i, int buf) {
        int s  = i / nk;
        int kt = i - s * nk;
        const __nv_bfloat16* pa = (s == 1 ? Alm : Ahm) + (size_t)(bm * 128) * Kdim + kt * 64;
        const __nv_bfloat16* pb = (s == 2 ? Blm : Bhm) + (size_t)(bn * 128) * Kdim + kt * 64;
        uint32_t base = sb + buf * STGB;
#pragma unroll
        for (int u = 0; u < 4; u++) {
            int row = lrow + 32 * u;
            uint32_t so = (uint32_t)(row * (HLD2 * 2) + lch * 16);
            size_t go = (size_t)row * Kdim + lch * 8;
            cp_async16(base + so,         pa + go);
            cp_async16(base + TILEB + so, pb + go);
        }
    };

    load_stage(0, 0);
    CP_COMMIT();

    for (int i = 0; i < nIter; i++) {
        const int buf = i & 1;
        if (i + 1 < nIter) {
            load_stage(i + 1, buf ^ 1);
            CP_COMMIT();
            CP_WAIT(1);
        } else {
            CP_WAIT(0);
        }
        __syncthreads();

        const uint32_t bA = sb + buf * STGB;
        const uint32_t bB = bA + TILEB;
        // per-warp invariant parts of ldsm addresses
        const uint32_t aRow = (uint32_t)((wm + (lane & 15)) * (HLD2 * 2) + (lane >> 4) * 16);
        const uint32_t bRow = (uint32_t)((wn + (lane & 7) + ((lane >> 4) & 1) * 8) * (HLD2 * 2)
                                          + ((lane >> 3) & 1) * 16);

#pragma unroll
        for (int k = 0; k < 64; k += 16) {
            uint32_t afr[2][4];
#pragma unroll
            for (int mi = 0; mi < 2; mi++)
                ldsm_x4(afr[mi], bA + aRow + mi * 16 * (HLD2 * 2) + k * 2);

            uint32_t bfr[8][2];
#pragma unroll
            for (int ni = 0; ni < 4; ni++) {
                uint32_t r[4];
                ldsm_x4(r, bB + bRow + ni * 16 * (HLD2 * 2) + k * 2);
                bfr[2 * ni][0]     = r[0];
                bfr[2 * ni][1]     = r[1];
                bfr[2 * ni + 1][0] = r[2];
                bfr[2 * ni + 1][1] = r[3];
            }
#pragma unroll
            for (int mi = 0; mi < 2; mi++)
#pragma unroll
                for (int nj = 0; nj < 8; nj++)
                    mma_bf16(acc[mi][nj], afr[mi], bfr[nj]);
        }
        __syncthreads();
    }

    // ---- epilogue ----
#pragma unroll
    for (int mi = 0; mi < 2; mi++) {
#pragma unroll
        for (int nj = 0; nj < 8; nj++) {
            int row0 = bm * 128 + wm + mi * 16 + (lane >> 2);
            int col  = bn * 128 + wn + nj * 8 + 2 * (lane & 3);
            float b0 = bias[col], b1 = bias[col + 1];
            float2 v0 = {acc[mi][nj][0] + b0, acc[mi][nj][1] + b1};
            float2 v1 = {acc[mi][nj][2] + b0, acc[mi][nj][3] + b1};
            if (mode >= 1) {
                v0.x = fmaxf(v0.x, 0.f); v0.y = fmaxf(v0.y, 0.f);
                v1.x = fmaxf(v1.x, 0.f); v1.y = fmaxf(v1.y, 0.f);
            }
            if (mode == 2) {
                float h0 = __bfloat162float(__float2bfloat16(v0.x));
                float h1 = __bfloat162float(__float2bfloat16(v0.y));
                float h2 = __bfloat162float(__float2bfloat16(v1.x));
                float h3 = __bfloat162float(__float2bfloat16(v1.y));
                *(uint32_t*)&Chi[(size_t)row0 * Ndim + col]       = cvt_bf2(h0, h1);
                *(uint32_t*)&Chi[(size_t)(row0 + 8) * Ndim + col] = cvt_bf2(h2, h3);
                *(uint32_t*)&Clo[(size_t)row0 * Ndim + col]       = cvt_bf2(v0.x - h0, v0.y - h1);
                *(uint32_t*)&Clo[(size_t)(row0 + 8) * Ndim + col] = cvt_bf2(v1.x - h2, v1.y - h3);
            } else {
                *(float2*)&C[(size_t)row0 * Ndim + col]       = v0;
                *(float2*)&C[(size_t)(row0 + 8) * Ndim + col] = v1;
            }
        }
    }
}

// ---------------------------------------------------------------------------
// HMMA flash attention (unchanged from R8, known-correct)
// ---------------------------------------------------------------------------
#define SWZ(row, ch) ((uint32_t)((row) * 128 + ((((ch) ^ ((row) & 7))) << 4)))

__global__ __launch_bounds__(128, 4)
void attn_hmma_kernel()
{
    __shared__ __nv_bfloat16 sQ[64 * 64];
    __shared__ __nv_bfloat16 sK[64 * 64];
    __shared__ __nv_bfloat16 sV[64 * 64];

    const int tid  = threadIdx.x;
    const int lane = tid & 31;
    const int wid  = tid >> 5;
    const int bh = blockIdx.x, qb = blockIdx.y;
    const int b = bh >> 4, h = bh & 15;
    const int g   = lane >> 2;
    const int tig = lane & 3;

    const uint32_t sQb = smem_u32(sQ);
    const uint32_t sKb = smem_u32(sK);
    const uint32_t sVb = smem_u32(sV);

    {
        const float* Qg = g_Q + ((size_t)(b * M_ + qb * 64)) * DMODEL + h * DK;
#pragma unroll
        for (int it = 0; it < 4; it++) {
            int task = tid + 128 * it;
            int row = task >> 3, ch = task & 7;
            const float* src = Qg + (size_t)row * DMODEL + ch * 8;
            float4 v0 = *(const float4*)src;
            float4 v1 = *(const float4*)(src + 4);
            uint4 d;
            d.x = cvt_bf2(v0.x, v0.y);
            d.y = cvt_bf2(v0.z, v0.w);
            d.z = cvt_bf2(v1.x, v1.y);
            d.w = cvt_bf2(v1.z, v1.w);
            *(uint4*)((char*)sQ + SWZ(row, ch)) = d;
        }
    }
    __syncthreads();

    uint32_t qa[4][4];
#pragma unroll
    for (int kc = 0; kc < 4; kc++) {
        int row = wid * 16 + (lane & 15);
        int ch  = 2 * kc + (lane >> 4);
        ldsm_x4(qa[kc], sQb + SWZ(row, ch));
    }

    const int qrow0 = b * M_ + qb * 64 + wid * 16;
    const bool mq0 = g_mask[qrow0 + g] != 0;
    const bool mq8 = g_mask[qrow0 + g + 8] != 0;

    float o[8][4];
    float m0 = -1e30f, m8 = -1e30f, l0 = 0.0f, l8 = 0.0f;
#pragma unroll
    for (int nt = 0; nt < 8; nt++)
#pragma unroll
        for (int q = 0; q < 4; q++) o[nt][q] = 0.0f;

    const unsigned FULL = 0xffffffffu;

    for (int kb = 0; kb < M_ / 64; kb++) {
        __syncthreads();

        {
            const float* Kg = g_K + ((size_t)(b * M_ + kb * 64)) * DMODEL + h * DK;
            const float* Vg = g_V + ((size_t)(b * M_ + kb * 64)) * DMODEL + h * DK;
#pragma unroll
            for (int it = 0; it < 4; it++) {
                int task = tid + 128 * it;
                int row = task >> 3, ch = task & 7;
                size_t goff = (size_t)row * DMODEL + ch * 8;
                uint32_t soff = SWZ(row, ch);
                float4 k0v = *(const float4*)(Kg + goff);
                float4 k1v = *(const float4*)(Kg + goff + 4);
                uint4 dk;
                dk.x = cvt_bf2(k0v.x, k0v.y);
                dk.y = cvt_bf2(k0v.z, k0v.w);
                dk.z = cvt_bf2(k1v.x, k1v.y);
                dk.w = cvt_bf2(k1v.z, k1v.w);
                *(uint4*)((char*)sK + soff) = dk;
                float4 v0v = *(const float4*)(Vg + goff);
                float4 v1v = *(const float4*)(Vg + goff + 4);
                uint4 dv;
                dv.x = cvt_bf2(v0v.x, v0v.y);
                dv.y = cvt_bf2(v0v.z, v0v.w);
                dv.z = cvt_bf2(v1v.x, v1v.y);
                dv.w = cvt_bf2(v1v.z, v1v.w);
                *(uint4*)((char*)sV + soff) = dv;
            }
        }
        __syncthreads();

        float s[8][4];
#pragma unroll
        for (int nt = 0; nt < 8; nt++)
#pragma unroll
            for (int q = 0; q < 4; q++) s[nt][q] = 0.0f;

#pragma unroll
        for (int kc = 0; kc < 4; kc++) {
#pragma unroll
            for (int ntp = 0; ntp < 4; ntp++) {
                uint32_t kbf[4];
                int rowk = ntp * 16 + ((lane >> 1) & 8) + (lane & 7);
                int chk  = 2 * kc + ((lane >> 3) & 1);
                ldsm_x4(kbf, sKb + SWZ(rowk, chk));
                mma_bf16(s[2 * ntp],     qa[kc], kbf);
                mma_bf16(s[2 * ntp + 1], qa[kc], kbf + 2);
            }
        }

        const unsigned char* mkp = g_mask + b * M_ + kb * 64;
        float mn0 = m0, mn8 = m8;
#pragma unroll
        for (int nt = 0; nt < 8; nt++) {
            int c0 = nt * 8 + 2 * tig;
            bool k0 = mkp[c0] != 0, k1 = mkp[c0 + 1] != 0;
            s[nt][0] = (mq0 && k0) ? s[nt][0] * INV_D : MASKF;
            s[nt][1] = (mq0 && k1) ? s[nt][1] * INV_D : MASKF;
            s[nt][2] = (mq8 && k0) ? s[nt][2] * INV_D : MASKF;
            s[nt][3] = (mq8 && k1) ? s[nt][3] * INV_D : MASKF;
            mn0 = fmaxf(mn0, fmaxf(s[nt][0], s[nt][1]));
            mn8 = fmaxf(mn8, fmaxf(s[nt][2], s[nt][3]));
        }
        mn0 = fmaxf(mn0, __shfl_xor_sync(FULL, mn0, 1));
        mn0 = fmaxf(mn0, __shfl_xor_sync(FULL, mn0, 2));
        mn8 = fmaxf(mn8, __shfl_xor_sync(FULL, mn8, 1));
        mn8 = fmaxf(mn8, __shfl_xor_sync(FULL, mn8, 2));

        float corr0 = __expf(m0 - mn0);
        float corr8 = __expf(m8 - mn8);
        m0 = mn0; m8 = mn8;

        float sum0 = 0.0f, sum8 = 0.0f;
#pragma unroll
        for (int nt = 0; nt < 8; nt++) {
            s[nt][0] = __expf(s[nt][0] - mn0);
            s[nt][1] = __expf(s[nt][1] - mn0);
            s[nt][2] = __expf(s[nt][2] - mn8);
            s[nt][3] = __expf(s[nt][3] - mn8);
            sum0 += s[nt][0] + s[nt][1];
            sum8 += s[nt][2] + s[nt][3];
        }
        sum0 += __shfl_xor_sync(FULL, sum0, 1);
        sum0 += __shfl_xor_sync(FULL, sum0, 2);
        sum8 += __shfl_xor_sync(FULL, sum8, 1);
        sum8 += __shfl_xor_sync(FULL, sum8, 2);
        l0 = l0 * corr0 + sum0;
        l8 = l8 * corr8 + sum8;

#pragma unroll
        for (int nt = 0; nt < 8; nt++) {
            o[nt][0] *= corr0; o[nt][1] *= corr0;
            o[nt][2] *= corr8; o[nt][3] *= corr8;
        }
        uint32_t p[4][4];
#pragma unroll
        for (int kc = 0; kc < 4; kc++) {
            p[kc][0] = cvt_bf2(s[2 * kc][0],     s[2 * kc][1]);
            p[kc][1] = cvt_bf2(s[2 * kc][2],     s[2 * kc][3]);
            p[kc][2] = cvt_bf2(s[2 * kc + 1][0], s[2 * kc + 1][1]);
            p[kc][3] = cvt_bf2(s[2 * kc + 1][2], s[2 * kc + 1][3]);
        }

#pragma unroll
        for (int kc = 0; kc < 4; kc++) {
#pragma unroll
            for (int ntp = 0; ntp < 4; ntp++) {
                uint32_t vbf[4];
                int rowv = kc * 16 + (lane & 15);
                int chv  = 2 * ntp + (lane >> 4);
                ldsm_x4_t(vbf, sVb + SWZ(rowv, chv));
                mma_bf16(o[2 * ntp],     p[kc], vbf);
                mma_bf16(o[2 * ntp + 1], p[kc], vbf + 2);
            }
        }
    }

    float inv0 = 1.0f / l0, inv8 = 1.0f / l8;
    float* Og = g_AO + ((size_t)(b * M_ + qb * 64 + wid * 16)) * DMODEL + h * DK;
#pragma unroll
    for (int nt = 0; nt < 8; nt++) {
        int c0 = nt * 8 + 2 * tig;
        float2 w0 = {o[nt][0] * inv0, o[nt][1] * inv0};
        float2 w1 = {o[nt][2] * inv8, o[nt][3] * inv8};
        *(float2*)&Og[(size_t)g * DMODEL + c0]       = w0;
        *(float2*)&Og[(size_t)(g + 8) * DMODEL + c0] = w1;
    }
}

// ---------------------------------------------------------------------------
// out = LayerNorm(a + b) * gamma + beta; optionally also emit bf16 hi/lo split
// ---------------------------------------------------------------------------
__global__ __launch_bounds__(256)
void add_ln_kernel(const float* __restrict__ A, const float* __restrict__ Bv,
                   const float* __restrict__ gamma, const float* __restrict__ beta,
                   float* __restrict__ Out,
                   __nv_bfloat16* __restrict__ Shi, __nv_bfloat16* __restrict__ Slo,
                   int emitSplit)
{
    const int row = blockIdx.x;
    const int t   = threadIdx.x;
    const float4* a4 = (const float4*)(A  + (size_t)row * DMODEL);
    const float4* b4 = (const float4*)(Bv + (size_t)row * DMODEL);

    float4 av = a4[t], bv = b4[t];
    float s0 = av.x + bv.x, s1 = av.y + bv.y, s2 = av.z + bv.z, s3 = av.w + bv.w;

    float sum = s0 + s1 + s2 + s3;
    float sq  = s0 * s0 + s1 * s1 + s2 * s2 + s3 * s3;
#pragma unroll
    for (int o = 16; o; o >>= 1) {
        sum += __shfl_xor_sync(0xffffffffu, sum, o);
        sq  += __shfl_xor_sync(0xffffffffu, sq,  o);
    }
    __shared__ float ssum[8], ssq[8];
    __shared__ float smu, srs;
    int wid = t >> 5, lane = t & 31;
    if (lane == 0) { ssum[wid] = sum; ssq[wid] = sq; }
    __syncthreads();
    if (t < 32) {
        float s2_ = (t < 8) ? ssum[t] : 0.0f;
        float q2_ = (t < 8) ? ssq[t]  : 0.0f;
#pragma unroll
        for (int o = 4; o; o >>= 1) {
            s2_ += __shfl_xor_sync(0xffffffffu, s2_, o);
            q2_ += __shfl_xor_sync(0xffffffffu, q2_, o);
        }
        if (t == 0) {
            float mu  = s2_ * (1.0f / DMODEL);
            float var = q2_ * (1.0f / DMODEL) - mu * mu;
            smu = mu;
            srs = rsqrtf(var + LN_EPS);
        }
    }
    __syncthreads();
    float mu = smu, rs = srs;
    float4 g = ((const float4*)gamma)[t];
    float4 be = ((const float4*)beta)[t];
    float4 o;
    o.x = (s0 - mu) * rs * g.x + be.x;
    o.y = (s1 - mu) * rs * g.y + be.y;
    o.z = (s2 - mu) * rs * g.z + be.z;
    o.w = (s3 - mu) * rs * g.w + be.w;
    ((float4*)(Out + (size_t)row * DMODEL))[t] = o;

    if (emitSplit) {
        float h0 = __bfloat162float(__float2bfloat16(o.x));
        float h1 = __bfloat162float(__float2bfloat16(o.y));
        float h2 = __bfloat162float(__float2bfloat16(o.z));
        float h3 = __bfloat162float(__float2bfloat16(o.w));
        size_t off = (size_t)row * DMODEL + t * 4;
        *(uint32_t*)&Shi[off]     = cvt_bf2(h0, h1);
        *(uint32_t*)&Shi[off + 2] = cvt_bf2(h2, h3);
        *(uint32_t*)&Slo[off]     = cvt_bf2(o.x - h0, o.y - h1);
        *(uint32_t*)&Slo[off + 2] = cvt_bf2(o.z - h2, o.w - h3);
    }
}

// ---------------------------------------------------------------------------
// Launch
// ---------------------------------------------------------------------------
extern "C" void kernel_launch(void* const* d_in, const int* in_sizes, int n_in,
                              void* d_out, int out_size)
{
    (void)in_sizes; (void)n_in; (void)out_size;
    const float*         x    = (const float*)d_in[0];
    const unsigned char* mb   = (const unsigned char*)d_in[1];
    const float* Wq = (const float*)d_in[2];
    const float* bq = (const float*)d_in[3];
    const float* Wk = (const float*)d_in[4];
    const float* bk = (const float*)d_in[5];
    const float* Wv = (const float*)d_in[6];
    const float* bv = (const float*)d_in[7];
    const float* W1 = (const float*)d_in[8];
    const float* b1 = (const float*)d_in[9];
    const float* W2 = (const float*)d_in[10];
    const float* b2 = (const float*)d_in[11];
    const float* g1 = (const float*)d_in[12];
    const float* be1 = (const float*)d_in[13];
    const float* g2 = (const float*)d_in[14];
    const float* be2 = (const float*)d_in[15];
    float* out = (float*)d_out;

    float *pQ, *pK, *pV, *pAO, *pH1, *pF1, *pF2;
    __nv_bfloat16 *pAh, *pAl, *pBh, *pBl;
    cudaGetSymbolAddress((void**)&pQ,  g_Q);
    cudaGetSymbolAddress((void**)&pK,  g_K);
    cudaGetSymbolAddress((void**)&pV,  g_V);
    cudaGetSymbolAddress((void**)&pAO, g_AO);
    cudaGetSymbolAddress((void**)&pH1, g_H1);
    cudaGetSymbolAddress((void**)&pF1, g_F1);
    cudaGetSymbolAddress((void**)&pF2, g_F2);
    cudaGetSymbolAddress((void**)&pAh, g_Ah);
    cudaGetSymbolAddress((void**)&pAl, g_Al);
    cudaGetSymbolAddress((void**)&pBh, g_Bh);
    cudaGetSymbolAddress((void**)&pBl, g_Bl);

    // F1 bf16 split planes alias g_F1's 64MB
    __nv_bfloat16* pF1h = (__nv_bfloat16*)pF1;
    __nv_bfloat16* pF1l = pF1h + (size_t)ROWS * FF;

    cudaFuncSetAttribute(hgemm_bf16x3_kernel,
                         cudaFuncAttributeMaxDynamicSharedMemorySize, GEMM_SMEM);

    mask_norm_kernel<<<1, 256>>>(mb, ROWS);

    // ---- split x (A operand for QKV) ----
    conv_split_kernel<<<(ROWS * DMODEL / 4 + 255) / 256, 256>>>(x, pAh, pAl, ROWS * DMODEL / 4);

    dim3 tg32(DMODEL / 32, DMODEL / 32);
    dim3 tb(32, 8);
    dim3 gqkv(DMODEL / 128, ROWS / 128);

    convT_split_kernel<<<tg32, tb>>>(Wq, pBh, pBl, DMODEL, DMODEL);
    hgemm_bf16x3_kernel<<<gqkv, 256, GEMM_SMEM>>>(pAh, pAl, pBh, pBl, bq, pQ, 0, 0, DMODEL, DMODEL, 0);
    convT_split_kernel<<<tg32, tb>>>(Wk, pBh, pBl, DMODEL, DMODEL);
    hgemm_bf16x3_kernel<<<gqkv, 256, GEMM_SMEM>>>(pAh, pAl, pBh, pBl, bk, pK, 0, 0, DMODEL, DMODEL, 0);
    convT_split_kernel<<<tg32, tb>>>(Wv, pBh, pBl, DMODEL, DMODEL);
    hgemm_bf16x3_kernel<<<gqkv, 256, GEMM_SMEM>>>(pAh, pAl, pBh, pBl, bv, pV, 0, 0, DMODEL, DMODEL, 0);

    // ---- attention (HMMA bf16) ----
    attn_hmma_kernel<<<dim3(B_ * NH, M_ / 64), 128>>>();

    // ---- h1 = LN(x + attn_out), fused split into g_Ah/g_Al ----
    add_ln_kernel<<<ROWS, 256>>>(x, pAO, g1, be1, pH1, pAh, pAl, 1);

    // ---- FF1: relu(h1 @ W1 + b1), epilogue writes bf16 hi/lo split ----
    convT_split_kernel<<<dim3(FF / 32, DMODEL / 32), tb>>>(W1, pBh, pBl, DMODEL, FF);
    hgemm_bf16x3_kernel<<<dim3(FF / 128, ROWS / 128), 256, GEMM_SMEM>>>(
        pAh, pAl, pBh, pBl, b1, 0, pF1h, pF1l, FF, DMODEL, 2);

    // ---- FF2: f1 @ W2 + b2 ----
    convT_split_kernel<<<dim3(DMODEL / 32, FF / 32), tb>>>(W2, pBh, pBl, FF, DMODEL);
    hgemm_bf16x3_kernel<<<dim3(DMODEL / 128, ROWS / 128), 256, GEMM_SMEM>>>(
        pF1h, pF1l, pBh, pBl, b2, pF2, 0, 0, DMODEL, FF, 0);

    // ---- out = LN(h1 + ff) ----
    add_ln_kernel<<<ROWS, 256>>>(pH1, pF2, g2, be2, out, 0, 0, 0);
}

// round 14
// speedup vs baseline: 1.6084x; 1.6084x over previous
#include <cuda_runtime.h>
#include <cuda_bf16.h>
#include <math.h>
#include <stdint.h>

// ---------------------------------------------------------------------------
// Problem constants
// ---------------------------------------------------------------------------
#define B_      2
#define M_      2048
#define DMODEL  1024
#define NH      16
#define DK      64
#define FF      4096
#define ROWS    (B_ * M_)          // 4096
#define MASKF   (-9.765625e11f)    // MASK_VAL / D_MODEL
#define INV_D   (1.0f / 1024.0f)
#define LN_EPS  1e-5f

// ---------------------------------------------------------------------------
// Scratch (allocation-free: __device__ globals)
// ---------------------------------------------------------------------------
__device__ float g_Q [ROWS * DMODEL];
__device__ float g_K [ROWS * DMODEL];
__device__ float g_V [ROWS * DMODEL];
__device__ float g_AO[ROWS * DMODEL];
__device__ float g_H1[ROWS * DMODEL];
__device__ float g_F1[ROWS * FF];        // aliased as two bf16 planes (hi|lo)
__device__ float g_F2[ROWS * DMODEL];
__device__ unsigned char g_mask[ROWS];
__device__ __nv_bfloat16 g_Ah[ROWS * DMODEL];
__device__ __nv_bfloat16 g_Al[ROWS * DMODEL];
__device__ __nv_bfloat16 g_Bh[FF * DMODEL];
__device__ __nv_bfloat16 g_Bl[FF * DMODEL];

// ---------------------------------------------------------------------------
// Helpers
// ---------------------------------------------------------------------------
__device__ __forceinline__ uint32_t smem_u32(const void* p) {
    uint32_t a;
    asm("{ .reg .u64 t; cvta.to.shared.u64 t, %1; cvt.u32.u64 %0, t; }"
        : "=r"(a) : "l"(p));
    return a;
}

__device__ __forceinline__ void cp_async16(uint32_t saddr, const void* g) {
    asm volatile("cp.async.cg.shared.global [%0], [%1], 16;"
                 :: "r"(saddr), "l"(g));
}
#define CP_COMMIT()  asm volatile("cp.async.commit_group;" ::: "memory")
#define CP_WAIT(n)   asm volatile("cp.async.wait_group %0;" :: "n"(n) : "memory")

__device__ __forceinline__ void ldsm_x4(uint32_t* r, uint32_t addr) {
    asm volatile("ldmatrix.sync.aligned.m8n8.x4.shared.b16 {%0,%1,%2,%3}, [%4];"
                 : "=r"(r[0]), "=r"(r[1]), "=r"(r[2]), "=r"(r[3]) : "r"(addr));
}

__device__ __forceinline__ void ldsm_x4_t(uint32_t* r, uint32_t addr) {
    asm volatile("ldmatrix.sync.aligned.m8n8.x4.trans.shared.b16 {%0,%1,%2,%3}, [%4];"
                 : "=r"(r[0]), "=r"(r[1]), "=r"(r[2]), "=r"(r[3]) : "r"(addr));
}

__device__ __forceinline__ void mma_bf16(float* c, const uint32_t* a, const uint32_t* b) {
    asm volatile(
        "mma.sync.aligned.m16n8k16.row.col.f32.bf16.bf16.f32 "
        "{%0,%1,%2,%3}, {%4,%5,%6,%7}, {%8,%9}, {%0,%1,%2,%3};"
        : "+f"(c[0]), "+f"(c[1]), "+f"(c[2]), "+f"(c[3])
        : "r"(a[0]), "r"(a[1]), "r"(a[2]), "r"(a[3]), "r"(b[0]), "r"(b[1]));
}

// pack two fp32 -> bf16x2 (first arg in low half)
__device__ __forceinline__ uint32_t cvt_bf2(float lo, float hi) {
    uint32_t r;
    asm("cvt.rn.bf16x2.f32 %0, %1, %2;" : "=r"(r) : "f"(hi), "f"(lo));
    return r;
}

// ---------------------------------------------------------------------------
// Mask normalization (unchanged, known-correct)
// ---------------------------------------------------------------------------
__global__ void mask_norm_kernel(const unsigned char* __restrict__ mb, int nelem)
{
    __shared__ int s_gt1, s_off;
    int t = threadIdx.x;
    if (t == 0) { s_gt1 = 0; s_off = 0; }
    __syncthreads();
    int gt1 = 0, off = 0;
    for (int i = t; i < nelem; i += blockDim.x) {
        unsigned char v = mb[i];
        if (v > 1) gt1 = 1;
        if ((i & 3) && v) off = 1;
    }
    if (gt1) atomicOr(&s_gt1, 1);
    if (off) atomicOr(&s_off, 1);
    __syncthreads();
    bool u8 = (!s_gt1) && s_off;
    if (u8) {
        for (int i = t; i < nelem; i += blockDim.x)
            g_mask[i] = mb[i] ? 1 : 0;
    } else {
        const int* mi = (const int*)mb;
        for (int i = t; i < nelem; i += blockDim.x)
            g_mask[i] = mi[i] ? 1 : 0;
    }
}

// ---------------------------------------------------------------------------
// fp32 -> bf16 hi/lo split (x only)
// ---------------------------------------------------------------------------
__global__ __launch_bounds__(256)
void conv_split_kernel(const float* __restrict__ src,
                       __nv_bfloat16* __restrict__ hi, __nv_bfloat16* __restrict__ lo,
                       int n4)
{
    int i = blockIdx.x * 256 + threadIdx.x;
    if (i >= n4) return;
    float4 v = ((const float4*)src)[i];
    __nv_bfloat16 h0 = __float2bfloat16(v.x);
    __nv_bfloat16 h1 = __float2bfloat16(v.y);
    __nv_bfloat16 h2 = __float2bfloat16(v.z);
    __nv_bfloat16 h3 = __float2bfloat16(v.w);
    __nv_bfloat16 l0 = __float2bfloat16(v.x - __bfloat162float(h0));
    __nv_bfloat16 l1 = __float2bfloat16(v.y - __bfloat162float(h1));
    __nv_bfloat16 l2 = __float2bfloat16(v.z - __bfloat162float(h2));
    __nv_bfloat16 l3 = __float2bfloat16(v.w - __bfloat162float(h3));
    __nv_bfloat162* H = (__nv_bfloat162*)hi;
    __nv_bfloat162* L = (__nv_bfloat162*)lo;
    H[2 * i]     = __nv_bfloat162(h0, h1);
    H[2 * i + 1] = __nv_bfloat162(h2, h3);
    L[2 * i]     = __nv_bfloat162(l0, l1);
    L[2 * i + 1] = __nv_bfloat162(l2, l3);
}

// ---------------------------------------------------------------------------
// Weight transpose + split: src[K,N] fp32 -> hi/lo [N,K] bf16
// ---------------------------------------------------------------------------
__global__ __launch_bounds__(256)
void convT_split_kernel(const float* __restrict__ src,
                        __nv_bfloat16* __restrict__ hi, __nv_bfloat16* __restrict__ lo,
                        int Kdim, int Ndim)
{
    __shared__ float tile[32][33];
    int n0 = blockIdx.x * 32, k0 = blockIdx.y * 32;
    int x = threadIdx.x, y = threadIdx.y;   // 32 x 8
#pragma unroll
    for (int j = 0; j < 32; j += 8)
        tile[y + j][x] = src[(size_t)(k0 + y + j) * Ndim + n0 + x];
    __syncthreads();
#pragma unroll
    for (int j = 0; j < 32; j += 8) {
        float v = tile[x][y + j];
        __nv_bfloat16 h = __float2bfloat16(v);
        __nv_bfloat16 l = __float2bfloat16(v - __bfloat162float(h));
        size_t o = (size_t)(n0 + y + j) * Kdim + k0 + x;
        hi[o] = h; lo[o] = l;
    }
}

// ---------------------------------------------------------------------------
// HMMA GEMM v4: BK=32 triple-pass dataflow with 3-stage cp.async pipeline and
// register double-buffered fragments (one __syncthreads per iteration, every
// ldsm overlapped by 16 MMAs).
// Dynamic smem: 3 stages x (A 128x40 + B 128x40) bf16 = 61440 bytes.
// mode: 0 = fp32 out + bias; 1 = +relu fp32; 2 = +relu, write bf16 hi/lo split.
// ---------------------------------------------------------------------------
#define HLD    40                       // padded row stride (bf16 elems)
#define ATILE  (128 * HLD * 2)          // 10240 bytes
#define STG3   (2 * ATILE)              // A+B per stage = 20480
#define GEMM_SMEM (3 * STG3)            // 61440

__global__ __launch_bounds__(256, 2)
void hgemm_bf16x3_kernel(const __nv_bfloat16* __restrict__ Ahm,
                         const __nv_bfloat16* __restrict__ Alm,
                         const __nv_bfloat16* __restrict__ Bhm,
                         const __nv_bfloat16* __restrict__ Blm,
                         const float* __restrict__ bias,
                         float* __restrict__ C,
                         __nv_bfloat16* __restrict__ Chi,
                         __nv_bfloat16* __restrict__ Clo,
                         int Ndim, int Kdim, int mode)
{
    extern __shared__ char dsm[];
    const uint32_t sb = smem_u32(dsm);

    const int tid  = threadIdx.x;
    const int lane = tid & 31;
    const int wid  = tid >> 5;
    const int bm = blockIdx.y, bn = blockIdx.x;
    const int wm = (wid >> 1) * 32;
    const int wn = (wid & 1) * 64;

    const int nk = Kdim >> 5;
    const int nIter = 3 * nk;

    const int lrow = tid >> 2;          // 0..63
    const int lch  = tid & 3;

    float acc[2][8][4];
#pragma unroll
    for (int mi = 0; mi < 2; mi++)
#pragma unroll
        for (int nj = 0; nj < 8; nj++)
#pragma unroll
            for (int q = 0; q < 4; q++) acc[mi][nj][q] = 0.0f;

    // global stage loader (stage index i -> smem buffer buf)
    auto load_stage = [&](int i, int buf) {
        int s  = i / nk;
        int kt = i - s * nk;
        const __nv_bfloat16* pa = (s == 1 ? Alm : Ahm) + (size_t)(bm * 128) * Kdim + kt * 32;
        const __nv_bfloat16* pb = (s == 2 ? Blm : Bhm) + (size_t)(bn * 128) * Kdim + kt * 32;
        uint32_t base = sb + buf * STG3;
#pragma unroll
        for (int u = 0; u < 2; u++) {
            int row = lrow + 64 * u;
            uint32_t so = (uint32_t)(row * (HLD * 2) + lch * 16);
            size_t go = (size_t)row * Kdim + lch * 8;
            cp_async16(base + so,         pa + go);
            cp_async16(base + ATILE + so, pb + go);
        }
    };

    // per-warp invariant address pieces
    const uint32_t aBaseOff = (uint32_t)((wm + (lane & 15)) * (HLD * 2) + (lane >> 4) * 16);
    const uint32_t bBaseOff = (uint32_t)(ATILE
                        + (wn + (lane & 7) + ((lane >> 4) & 1) * 8) * (HLD * 2)
                        + ((lane >> 3) & 1) * 16);

    uint32_t fA0[2][4], fA1[2][4];
    uint32_t fB0[8][2], fB1[8][2];

#define LOAD_FRAGS(buf, k, fA, fB) do {                                         \
    uint32_t _sbase = sb + (buf) * STG3;                                        \
    _Pragma("unroll")                                                           \
    for (int mi = 0; mi < 2; mi++)                                              \
        ldsm_x4(fA[mi], _sbase + aBaseOff + mi * 16 * (HLD * 2) + (k) * 2);     \
    _Pragma("unroll")                                                           \
    for (int ni = 0; ni < 4; ni++) {                                            \
        uint32_t _r[4];                                                         \
        ldsm_x4(_r, _sbase + bBaseOff + ni * 16 * (HLD * 2) + (k) * 2);         \
        fB[2 * ni][0]     = _r[0];                                              \
        fB[2 * ni][1]     = _r[1];                                              \
        fB[2 * ni + 1][0] = _r[2];                                              \
        fB[2 * ni + 1][1] = _r[3];                                              \
    }                                                                           \
} while (0)

#define MMA_ALL(fA, fB) do {                                                    \
    _Pragma("unroll")                                                           \
    for (int mi = 0; mi < 2; mi++)                                              \
        _Pragma("unroll")                                                       \
        for (int nj = 0; nj < 8; nj++)                                          \
            mma_bf16(acc[mi][nj], fA[mi], fB[nj]);                              \
} while (0)

    // prologue: stages 0 and 1 in flight; stage 0 resident before frags
    load_stage(0, 0); CP_COMMIT();
    load_stage(1, 1); CP_COMMIT();
    CP_WAIT(1);
    __syncthreads();
    LOAD_FRAGS(0, 0, fA0, fB0);

    for (int i = 0; i < nIter; i++) {
        const int cur = i % 3;
        // k16 frags of current stage (overlap with k0 MMAs)
        LOAD_FRAGS(cur, 16, fA1, fB1);
        MMA_ALL(fA0, fB0);

        // issue stage i+2 into the buffer of stage i-1 (fully consumed:
        // its last read preceded iteration i-1's barrier)
        if (i + 2 < nIter) {
            load_stage(i + 2, (i + 2) % 3);
            CP_COMMIT();
            CP_WAIT(1);           // stage i+1 copies done (this thread)
        } else {
            CP_WAIT(0);           // drain tail
        }
        __syncthreads();          // publish stage i+1 to all warps

        if (i + 1 < nIter) {
            LOAD_FRAGS((i + 1) % 3, 0, fA0, fB0);   // k0 frags of next stage
        }
        MMA_ALL(fA1, fB1);
    }

#undef LOAD_FRAGS
#undef MMA_ALL

    // ---- epilogue ----
#pragma unroll
    for (int mi = 0; mi < 2; mi++) {
#pragma unroll
        for (int nj = 0; nj < 8; nj++) {
            int row0 = bm * 128 + wm + mi * 16 + (lane >> 2);
            int col  = bn * 128 + wn + nj * 8 + 2 * (lane & 3);
            float b0 = bias[col], b1 = bias[col + 1];
            float2 v0 = {acc[mi][nj][0] + b0, acc[mi][nj][1] + b1};
            float2 v1 = {acc[mi][nj][2] + b0, acc[mi][nj][3] + b1};
            if (mode >= 1) {
                v0.x = fmaxf(v0.x, 0.f); v0.y = fmaxf(v0.y, 0.f);
                v1.x = fmaxf(v1.x, 0.f); v1.y = fmaxf(v1.y, 0.f);
            }
            if (mode == 2) {
                float h0 = __bfloat162float(__float2bfloat16(v0.x));
                float h1 = __bfloat162float(__float2bfloat16(v0.y));
                float h2 = __bfloat162float(__float2bfloat16(v1.x));
                float h3 = __bfloat162float(__float2bfloat16(v1.y));
                *(uint32_t*)&Chi[(size_t)row0 * Ndim + col]       = cvt_bf2(h0, h1);
                *(uint32_t*)&Chi[(size_t)(row0 + 8) * Ndim + col] = cvt_bf2(h2, h3);
                *(uint32_t*)&Clo[(size_t)row0 * Ndim + col]       = cvt_bf2(v0.x - h0, v0.y - h1);
                *(uint32_t*)&Clo[(size_t)(row0 + 8) * Ndim + col] = cvt_bf2(v1.x - h2, v1.y - h3);
            } else {
                *(float2*)&C[(size_t)row0 * Ndim + col]       = v0;
                *(float2*)&C[(size_t)(row0 + 8) * Ndim + col] = v1;
            }
        }
    }
}

// ---------------------------------------------------------------------------
// HMMA flash attention (unchanged from R8, known-correct)
// ---------------------------------------------------------------------------
#define SWZ(row, ch) ((uint32_t)((row) * 128 + ((((ch) ^ ((row) & 7))) << 4)))

__global__ __launch_bounds__(128, 4)
void attn_hmma_kernel()
{
    __shared__ __nv_bfloat16 sQ[64 * 64];
    __shared__ __nv_bfloat16 sK[64 * 64];
    __shared__ __nv_bfloat16 sV[64 * 64];

    const int tid  = threadIdx.x;
    const int lane = tid & 31;
    const int wid  = tid >> 5;
    const int bh = blockIdx.x, qb = blockIdx.y;
    const int b = bh >> 4, h = bh & 15;
    const int g   = lane >> 2;
    const int tig = lane & 3;

    const uint32_t sQb = smem_u32(sQ);
    const uint32_t sKb = smem_u32(sK);
    const uint32_t sVb = smem_u32(sV);

    {
        const float* Qg = g_Q + ((size_t)(b * M_ + qb * 64)) * DMODEL + h * DK;
#pragma unroll
        for (int it = 0; it < 4; it++) {
            int task = tid + 128 * it;
            int row = task >> 3, ch = task & 7;
            const float* src = Qg + (size_t)row * DMODEL + ch * 8;
            float4 v0 = *(const float4*)src;
            float4 v1 = *(const float4*)(src + 4);
            uint4 d;
            d.x = cvt_bf2(v0.x, v0.y);
            d.y = cvt_bf2(v0.z, v0.w);
            d.z = cvt_bf2(v1.x, v1.y);
            d.w = cvt_bf2(v1.z, v1.w);
            *(uint4*)((char*)sQ + SWZ(row, ch)) = d;
        }
    }
    __syncthreads();

    uint32_t qa[4][4];
#pragma unroll
    for (int kc = 0; kc < 4; kc++) {
        int row = wid * 16 + (lane & 15);
        int ch  = 2 * kc + (lane >> 4);
        ldsm_x4(qa[kc], sQb + SWZ(row, ch));
    }

    const int qrow0 = b * M_ + qb * 64 + wid * 16;
    const bool mq0 = g_mask[qrow0 + g] != 0;
    const bool mq8 = g_mask[qrow0 + g + 8] != 0;

    float o[8][4];
    float m0 = -1e30f, m8 = -1e30f, l0 = 0.0f, l8 = 0.0f;
#pragma unroll
    for (int nt = 0; nt < 8; nt++)
#pragma unroll
        for (int q = 0; q < 4; q++) o[nt][q] = 0.0f;

    const unsigned FULL = 0xffffffffu;

    for (int kb = 0; kb < M_ / 64; kb++) {
        __syncthreads();

        {
            const float* Kg = g_K + ((size_t)(b * M_ + kb * 64)) * DMODEL + h * DK;
            const float* Vg = g_V + ((size_t)(b * M_ + kb * 64)) * DMODEL + h * DK;
#pragma unroll
            for (int it = 0; it < 4; it++) {
                int task = tid + 128 * it;
                int row = task >> 3, ch = task & 7;
                size_t goff = (size_t)row * DMODEL + ch * 8;
                uint32_t soff = SWZ(row, ch);
                float4 k0v = *(const float4*)(Kg + goff);
                float4 k1v = *(const float4*)(Kg + goff + 4);
                uint4 dk;
                dk.x = cvt_bf2(k0v.x, k0v.y);
                dk.y = cvt_bf2(k0v.z, k0v.w);
                dk.z = cvt_bf2(k1v.x, k1v.y);
                dk.w = cvt_bf2(k1v.z, k1v.w);
                *(uint4*)((char*)sK + soff) = dk;
                float4 v0v = *(const float4*)(Vg + goff);
                float4 v1v = *(const float4*)(Vg + goff + 4);
                uint4 dv;
                dv.x = cvt_bf2(v0v.x, v0v.y);
                dv.y = cvt_bf2(v0v.z, v0v.w);
                dv.z = cvt_bf2(v1v.x, v1v.y);
                dv.w = cvt_bf2(v1v.z, v1v.w);
                *(uint4*)((char*)sV + soff) = dv;
            }
        }
        __syncthreads();

        float s[8][4];
#pragma unroll
        for (int nt = 0; nt < 8; nt++)
#pragma unroll
            for (int q = 0; q < 4; q++) s[nt][q] = 0.0f;

#pragma unroll
        for (int kc = 0; kc < 4; kc++) {
#pragma unroll
            for (int ntp = 0; ntp < 4; ntp++) {
                uint32_t kbf[4];
                int rowk = ntp * 16 + ((lane >> 1) & 8) + (lane & 7);
                int chk  = 2 * kc + ((lane >> 3) & 1);
                ldsm_x4(kbf, sKb + SWZ(rowk, chk));
                mma_bf16(s[2 * ntp],     qa[kc], kbf);
                mma_bf16(s[2 * ntp + 1], qa[kc], kbf + 2);
            }
        }

        const unsigned char* mkp = g_mask + b * M_ + kb * 64;
        float mn0 = m0, mn8 = m8;
#pragma unroll
        for (int nt = 0; nt < 8; nt++) {
            int c0 = nt * 8 + 2 * tig;
            bool k0 = mkp[c0] != 0, k1 = mkp[c0 + 1] != 0;
            s[nt][0] = (mq0 && k0) ? s[nt][0] * INV_D : MASKF;
            s[nt][1] = (mq0 && k1) ? s[nt][1] * INV_D : MASKF;
            s[nt][2] = (mq8 && k0) ? s[nt][2] * INV_D : MASKF;
            s[nt][3] = (mq8 && k1) ? s[nt][3] * INV_D : MASKF;
            mn0 = fmaxf(mn0, fmaxf(s[nt][0], s[nt][1]));
            mn8 = fmaxf(mn8, fmaxf(s[nt][2], s[nt][3]));
        }
        mn0 = fmaxf(mn0, __shfl_xor_sync(FULL, mn0, 1));
        mn0 = fmaxf(mn0, __shfl_xor_sync(FULL, mn0, 2));
        mn8 = fmaxf(mn8, __shfl_xor_sync(FULL, mn8, 1));
        mn8 = fmaxf(mn8, __shfl_xor_sync(FULL, mn8, 2));

        float corr0 = __expf(m0 - mn0);
        float corr8 = __expf(m8 - mn8);
        m0 = mn0; m8 = mn8;

        float sum0 = 0.0f, sum8 = 0.0f;
#pragma unroll
        for (int nt = 0; nt < 8; nt++) {
            s[nt][0] = __expf(s[nt][0] - mn0);
            s[nt][1] = __expf(s[nt][1] - mn0);
            s[nt][2] = __expf(s[nt][2] - mn8);
            s[nt][3] = __expf(s[nt][3] - mn8);
            sum0 += s[nt][0] + s[nt][1];
            sum8 += s[nt][2] + s[nt][3];
        }
        sum0 += __shfl_xor_sync(FULL, sum0, 1);
        sum0 += __shfl_xor_sync(FULL, sum0, 2);
        sum8 += __shfl_xor_sync(FULL, sum8, 1);
        sum8 += __shfl_xor_sync(FULL, sum8, 2);
        l0 = l0 * corr0 + sum0;
        l8 = l8 * corr8 + sum8;

#pragma unroll
        for (int nt = 0; nt < 8; nt++) {
            o[nt][0] *= corr0; o[nt][1] *= corr0;
            o[nt][2] *= corr8; o[nt][3] *= corr8;
        }
        uint32_t p[4][4];
#pragma unroll
        for (int kc = 0; kc < 4; kc++) {
            p[kc][0] = cvt_bf2(s[2 * kc][0],     s[2 * kc][1]);
            p[kc][1] = cvt_bf2(s[2 * kc][2],     s[2 * kc][3]);
            p[kc][2] = cvt_bf2(s[2 * kc + 1][0], s[2 * kc + 1][1]);
            p[kc][3] = cvt_bf2(s[2 * kc + 1][2], s[2 * kc + 1][3]);
        }

#pragma unroll
        for (int kc = 0; kc < 4; kc++) {
#pragma unroll
            for (int ntp = 0; ntp < 4; ntp++) {
                uint32_t vbf[4];
                int rowv = kc * 16 + (lane & 15);
                int chv  = 2 * ntp + (lane >> 4);
                ldsm_x4_t(vbf, sVb + SWZ(rowv, chv));
                mma_bf16(o[2 * ntp],     p[kc], vbf);
                mma_bf16(o[2 * ntp + 1], p[kc], vbf + 2);
            }
        }
    }

    float inv0 = 1.0f / l0, inv8 = 1.0f / l8;
    float* Og = g_AO + ((size_t)(b * M_ + qb * 64 + wid * 16)) * DMODEL + h * DK;
#pragma unroll
    for (int nt = 0; nt < 8; nt++) {
        int c0 = nt * 8 + 2 * tig;
        float2 w0 = {o[nt][0] * inv0, o[nt][1] * inv0};
        float2 w1 = {o[nt][2] * inv8, o[nt][3] * inv8};
        *(float2*)&Og[(size_t)g * DMODEL + c0]       = w0;
        *(float2*)&Og[(size_t)(g + 8) * DMODEL + c0] = w1;
    }
}

// ---------------------------------------------------------------------------
// out = LayerNorm(a + b) * gamma + beta; optionally also emit bf16 hi/lo split
// ---------------------------------------------------------------------------
__global__ __launch_bounds__(256)
void add_ln_kernel(const float* __restrict__ A, const float* __restrict__ Bv,
                   const float* __restrict__ gamma, const float* __restrict__ beta,
                   float* __restrict__ Out,
                   __nv_bfloat16* __restrict__ Shi, __nv_bfloat16* __restrict__ Slo,
                   int emitSplit)
{
    const int row = blockIdx.x;
    const int t   = threadIdx.x;
    const float4* a4 = (const float4*)(A  + (size_t)row * DMODEL);
    const float4* b4 = (const float4*)(Bv + (size_t)row * DMODEL);

    float4 av = a4[t], bv = b4[t];
    float s0 = av.x + bv.x, s1 = av.y + bv.y, s2 = av.z + bv.z, s3 = av.w + bv.w;

    float sum = s0 + s1 + s2 + s3;
    float sq  = s0 * s0 + s1 * s1 + s2 * s2 + s3 * s3;
#pragma unroll
    for (int o = 16; o; o >>= 1) {
        sum += __shfl_xor_sync(0xffffffffu, sum, o);
        sq  += __shfl_xor_sync(0xffffffffu, sq,  o);
    }
    __shared__ float ssum[8], ssq[8];
    __shared__ float smu, srs;
    int wid = t >> 5, lane = t & 31;
    if (lane == 0) { ssum[wid] = sum; ssq[wid] = sq; }
    __syncthreads();
    if (t < 32) {
        float s2_ = (t < 8) ? ssum[t] : 0.0f;
        float q2_ = (t < 8) ? ssq[t]  : 0.0f;
#pragma unroll
        for (int o = 4; o; o >>= 1) {
            s2_ += __shfl_xor_sync(0xffffffffu, s2_, o);
            q2_ += __shfl_xor_sync(0xffffffffu, q2_, o);
        }
        if (t == 0) {
            float mu  = s2_ * (1.0f / DMODEL);
            float var = q2_ * (1.0f / DMODEL) - mu * mu;
            smu = mu;
            srs = rsqrtf(var + LN_EPS);
        }
    }
    __syncthreads();
    float mu = smu, rs = srs;
    float4 g = ((const float4*)gamma)[t];
    float4 be = ((const float4*)beta)[t];
    float4 o;
    o.x = (s0 - mu) * rs * g.x + be.x;
    o.y = (s1 - mu) * rs * g.y + be.y;
    o.z = (s2 - mu) * rs * g.z + be.z;
    o.w = (s3 - mu) * rs * g.w + be.w;
    ((float4*)(Out + (size_t)row * DMODEL))[t] = o;

    if (emitSplit) {
        float h0 = __bfloat162float(__float2bfloat16(o.x));
        float h1 = __bfloat162float(__float2bfloat16(o.y));
        float h2 = __bfloat162float(__float2bfloat16(o.z));
        float h3 = __bfloat162float(__float2bfloat16(o.w));
        size_t off = (size_t)row * DMODEL + t * 4;
        *(uint32_t*)&Shi[off]     = cvt_bf2(h0, h1);
        *(uint32_t*)&Shi[off + 2] = cvt_bf2(h2, h3);
        *(uint32_t*)&Slo[off]     = cvt_bf2(o.x - h0, o.y - h1);
        *(uint32_t*)&Slo[off + 2] = cvt_bf2(o.z - h2, o.w - h3);
    }
}

// ---------------------------------------------------------------------------
// Launch
// ---------------------------------------------------------------------------
extern "C" void kernel_launch(void* const* d_in, const int* in_sizes, int n_in,
                              void* d_out, int out_size)
{
    (void)in_sizes; (void)n_in; (void)out_size;
    const float*         x    = (const float*)d_in[0];
    const unsigned char* mb   = (const unsigned char*)d_in[1];
    const float* Wq = (const float*)d_in[2];
    const float* bq = (const float*)d_in[3];
    const float* Wk = (const float*)d_in[4];
    const float* bk = (const float*)d_in[5];
    const float* Wv = (const float*)d_in[6];
    const float* bv = (const float*)d_in[7];
    const float* W1 = (const float*)d_in[8];
    const float* b1 = (const float*)d_in[9];
    const float* W2 = (const float*)d_in[10];
    const float* b2 = (const float*)d_in[11];
    const float* g1 = (const float*)d_in[12];
    const float* be1 = (const float*)d_in[13];
    const float* g2 = (const float*)d_in[14];
    const float* be2 = (const float*)d_in[15];
    float* out = (float*)d_out;

    float *pQ, *pK, *pV, *pAO, *pH1, *pF1, *pF2;
    __nv_bfloat16 *pAh, *pAl, *pBh, *pBl;
    cudaGetSymbolAddress((void**)&pQ,  g_Q);
    cudaGetSymbolAddress((void**)&pK,  g_K);
    cudaGetSymbolAddress((void**)&pV,  g_V);
    cudaGetSymbolAddress((void**)&pAO, g_AO);
    cudaGetSymbolAddress((void**)&pH1, g_H1);
    cudaGetSymbolAddress((void**)&pF1, g_F1);
    cudaGetSymbolAddress((void**)&pF2, g_F2);
    cudaGetSymbolAddress((void**)&pAh, g_Ah);
    cudaGetSymbolAddress((void**)&pAl, g_Al);
    cudaGetSymbolAddress((void**)&pBh, g_Bh);
    cudaGetSymbolAddress((void**)&pBl, g_Bl);

    // F1 bf16 split planes alias g_F1's 64MB
    __nv_bfloat16* pF1h = (__nv_bfloat16*)pF1;
    __nv_bfloat16* pF1l = pF1h + (size_t)ROWS * FF;

    cudaFuncSetAttribute(hgemm_bf16x3_kernel,
                         cudaFuncAttributeMaxDynamicSharedMemorySize, GEMM_SMEM);

    mask_norm_kernel<<<1, 256>>>(mb, ROWS);

    // ---- split x (A operand for QKV) ----
    conv_split_kernel<<<(ROWS * DMODEL / 4 + 255) / 256, 256>>>(x, pAh, pAl, ROWS * DMODEL / 4);

    dim3 tg32(DMODEL / 32, DMODEL / 32);
    dim3 tb(32, 8);
    dim3 gqkv(DMODEL / 128, ROWS / 128);

    convT_split_kernel<<<tg32, tb>>>(Wq, pBh, pBl, DMODEL, DMODEL);
    hgemm_bf16x3_kernel<<<gqkv, 256, GEMM_SMEM>>>(pAh, pAl, pBh, pBl, bq, pQ, 0, 0, DMODEL, DMODEL, 0);
    convT_split_kernel<<<tg32, tb>>>(Wk, pBh, pBl, DMODEL, DMODEL);
    hgemm_bf16x3_kernel<<<gqkv, 256, GEMM_SMEM>>>(pAh, pAl, pBh, pBl, bk, pK, 0, 0, DMODEL, DMODEL, 0);
    convT_split_kernel<<<tg32, tb>>>(Wv, pBh, pBl, DMODEL, DMODEL);
    hgemm_bf16x3_kernel<<<gqkv, 256, GEMM_SMEM>>>(pAh, pAl, pBh, pBl, bv, pV, 0, 0, DMODEL, DMODEL, 0);

    // ---- attention (HMMA bf16) ----
    attn_hmma_kernel<<<dim3(B_ * NH, M_ / 64), 128>>>();

    // ---- h1 = LN(x + attn_out), fused split into g_Ah/g_Al ----
    add_ln_kernel<<<ROWS, 256>>>(x, pAO, g1, be1, pH1, pAh, pAl, 1);

    // ---- FF1: relu(h1 @ W1 + b1), epilogue writes bf16 hi/lo split ----
    convT_split_kernel<<<dim3(FF / 32, DMODEL / 32), tb>>>(W1, pBh, pBl, DMODEL, FF);
    hgemm_bf16x3_kernel<<<dim3(FF / 128, ROWS / 128), 256, GEMM_SMEM>>>(
        pAh, pAl, pBh, pBl, b1, 0, pF1h, pF1l, FF, DMODEL, 2);

    // ---- FF2: f1 @ W2 + b2 ----
    convT_split_kernel<<<dim3(DMODEL / 32, FF / 32), tb>>>(W2, pBh, pBl, FF, DMODEL);
    hgemm_bf16x3_kernel<<<dim3(DMODEL / 128, ROWS / 128), 256, GEMM_SMEM>>>(
        pF1h, pF1l, pBh, pBl, b2, pF2, 0, 0, DMODEL, FF, 0);

    // ---- out = LN(h1 + ff) ----
    add_ln_kernel<<<ROWS, 256>>>(pH1, pF2, g2, be2, out, 0, 0, 0);
}